// round 1
// baseline (speedup 1.0000x reference)
#include <cuda_runtime.h>
#include <math.h>

// Problem constants
#define NN        21
#define NN2       441      // 21*21
#define NFEAT     128
#define FC1_IN    441
#define FC1_OUT   512
#define FC2_IN    512
#define FC2_OUT   512
#define FC3_IN    512
#define FC3_OUT   256

// Scratch for the serial chain (allocation-free: __device__ globals)
__device__ float g_v[FC1_IN];
__device__ float g_x1[FC1_OUT];
__device__ float g_x2[FC2_OUT];
__device__ float g_prefetch_sink[64];

// ---------------------------------------------------------------------------
// Kernel 1: block 0 = full GCN front-end (only batch element 0 matters!)
//           blocks 1..N = prefetch FC weights into L2 (overlapped, no dep)
// ---------------------------------------------------------------------------
__global__ void gcn_front_kernel(const float* __restrict__ state,
                                 const int*   __restrict__ edge_index, int n_edges,
                                 const float* __restrict__ W1, const float* __restrict__ b1,
                                 const float* __restrict__ W2, const float* __restrict__ b2,
                                 const float* __restrict__ Wf1,
                                 const float* __restrict__ Wf2,
                                 const float* __restrict__ Wf3)
{
    if (blockIdx.x > 0) {
        // ---- L2 prefetch path: stream all FC weights with float4 loads ----
        const int nb = gridDim.x - 1;
        const int b  = blockIdx.x - 1;
        const int stride = nb * blockDim.x;
        const int base   = b * blockDim.x + threadIdx.x;
        float acc = 0.f;
        {
            const float4* p = (const float4*)Wf1;
            for (int i = base; i < (FC1_IN * FC1_OUT) / 4; i += stride) {
                float4 v = p[i]; acc += v.x + v.y + v.z + v.w;
            }
        }
        {
            const float4* p = (const float4*)Wf2;
            for (int i = base; i < (FC2_IN * FC2_OUT) / 4; i += stride) {
                float4 v = p[i]; acc += v.x + v.y + v.z + v.w;
            }
        }
        {
            const float4* p = (const float4*)Wf3;
            for (int i = base; i < (FC3_IN * FC3_OUT) / 4; i += stride) {
                float4 v = p[i]; acc += v.x + v.y + v.z + v.w;
            }
        }
        // deterministic side effect so loads are live
        if (threadIdx.x == 0) g_prefetch_sink[b] = acc;
        return;
    }

    // ---- GCN path: everything in shared memory ----
    __shared__ float sA[NN2];            // adjacency, then normalized adjacency
    __shared__ float sBufA[NN2];
    __shared__ float sBufB[NN2];
    __shared__ float sX[NN * NFEAT];     // state[0]  : 21 x 128
    __shared__ float sW1[NFEAT * NN];    // 128 x 21
    __shared__ float sW2[NN2];           // 21 x 21
    __shared__ float sb1[NN], sb2[NN], sdinv[NN];

    const int t = threadIdx.x;           // 512 threads

    if (t < NN2) sA[t] = 0.f;
    __syncthreads();

    // Scatter-add edges (duplicates accumulate, matching .at[].add)
    for (int e = t; e < n_edges; e += blockDim.x) {
        int r = edge_index[e];
        int c = edge_index[n_edges + e];
        atomicAdd(&sA[r * NN + c], 1.0f);
    }

    // Cooperative loads of batch-0 state and small weights
    for (int i = t; i < NN * NFEAT; i += blockDim.x) sX[i]  = state[i];
    for (int i = t; i < NFEAT * NN; i += blockDim.x) sW1[i] = W1[i];
    if (t < NN2) sW2[t] = W2[t];
    if (t < NN) { sb1[t] = b1[t]; sb2[t] = b2[t]; }
    __syncthreads();

    // Self loops (race-free after sync)
    if (t < NN) sA[t * NN + t] += 1.0f;
    __syncthreads();

    // deg[j] = column sums; dinv = 1/sqrt(deg)
    if (t < NN) {
        float d = 0.f;
        #pragma unroll
        for (int i = 0; i < NN; i++) d += sA[i * NN + t];
        sdinv[t] = (d > 0.f) ? rsqrtf(d) : 0.f;
    }
    __syncthreads();

    // A_norm[i][j] = dinv[i] * A[i][j] * dinv[j]
    if (t < NN2) {
        int i = t / NN, j = t % NN;
        sA[t] *= sdinv[i] * sdinv[j];
    }
    __syncthreads();

    // h1 = X @ W1   (21x128 @ 128x21)
    if (t < NN2) {
        int i = t / NN, j = t % NN;
        float acc = 0.f;
        #pragma unroll 8
        for (int f = 0; f < NFEAT; f++) acc += sX[i * NFEAT + f] * sW1[f * NN + j];
        sBufA[t] = acc;
    }
    __syncthreads();

    // g1 = A_norm @ h1 + b1
    if (t < NN2) {
        int i = t / NN, j = t % NN;
        float acc = sb1[j];
        #pragma unroll
        for (int k = 0; k < NN; k++) acc += sA[i * NN + k] * sBufA[k * NN + j];
        sBufB[t] = acc;
    }
    __syncthreads();

    // h2 = g1 @ W2
    if (t < NN2) {
        int i = t / NN, j = t % NN;
        float acc = 0.f;
        #pragma unroll
        for (int f = 0; f < NN; f++) acc += sBufB[i * NN + f] * sW2[f * NN + j];
        sBufA[t] = acc;
    }
    __syncthreads();

    // g2 = A_norm @ h2 + b2  ->  v (row-major flatten matches reshape(B,-1)[0])
    if (t < NN2) {
        int i = t / NN, j = t % NN;
        float acc = sb2[j];
        #pragma unroll
        for (int k = 0; k < NN; k++) acc += sA[i * NN + k] * sBufA[k * NN + j];
        g_v[t] = acc;
    }
}

// ---------------------------------------------------------------------------
// Generic FC layer: out[j] = relu( sum_k x[k] * W[k*Nout + j] + b[j] )
// Grid: Nout/32 blocks, 256 threads. Warp w handles K-slice k = w, w+8, ...
// -> for a fixed k, lanes read 32 consecutive W columns (coalesced 128 B).
// ---------------------------------------------------------------------------
__global__ void fc_relu_kernel(const float* __restrict__ x_in, int K,
                               const float* __restrict__ W,
                               const float* __restrict__ bias,
                               float* __restrict__ x_out, int Nout)
{
    __shared__ float sx[512];
    __shared__ float red[256];

    const int t  = threadIdx.x;
    const int jj = t & 31;       // output within block
    const int kg = t >> 5;       // k-group (0..7)
    const int j  = blockIdx.x * 32 + jj;

    for (int i = t; i < K; i += 256) sx[i] = x_in[i];
    __syncthreads();

    float acc = 0.f;
    #pragma unroll 4
    for (int k = kg; k < K; k += 8)
        acc += sx[k] * W[k * Nout + j];

    red[t] = acc;
    __syncthreads();

    if (t < 32) {
        float s = red[t];
        #pragma unroll
        for (int g = 1; g < 8; g++) s += red[g * 32 + t];
        s += bias[j];
        x_out[j] = fmaxf(s, 0.f);
    }
}

// ---------------------------------------------------------------------------
extern "C" void kernel_launch(void* const* d_in, const int* in_sizes, int n_in,
                              void* d_out, int out_size)
{
    const float* state = (const float*)d_in[0];
    const int*   edges = (const int*)  d_in[1];
    const int n_edges  = in_sizes[1] / 2;

    const float* W1  = (const float*)d_in[2];
    const float* b1  = (const float*)d_in[3];
    const float* W2  = (const float*)d_in[4];
    const float* b2  = (const float*)d_in[5];
    const float* Wf1 = (const float*)d_in[6];
    const float* bf1 = (const float*)d_in[7];
    const float* Wf2 = (const float*)d_in[8];
    const float* bf2 = (const float*)d_in[9];
    const float* Wf3 = (const float*)d_in[10];
    const float* bf3 = (const float*)d_in[11];
    float* out = (float*)d_out;

    void *pv = nullptr, *px1 = nullptr, *px2 = nullptr;
    cudaGetSymbolAddress(&pv,  g_v);
    cudaGetSymbolAddress(&px1, g_x1);
    cudaGetSymbolAddress(&px2, g_x2);

    // 1 GCN block + 20 L2-prefetch blocks
    gcn_front_kernel<<<21, 512>>>(state, edges, n_edges,
                                  W1, b1, W2, b2, Wf1, Wf2, Wf3);

    fc_relu_kernel<<<FC1_OUT / 32, 256>>>((const float*)pv,  FC1_IN, Wf1, bf1, (float*)px1, FC1_OUT);
    fc_relu_kernel<<<FC2_OUT / 32, 256>>>((const float*)px1, FC2_IN, Wf2, bf2, (float*)px2, FC2_OUT);
    fc_relu_kernel<<<FC3_OUT / 32, 256>>>((const float*)px2, FC3_IN, Wf3, bf3, out,         FC3_OUT);
}

// round 2
// speedup vs baseline: 1.3105x; 1.3105x over previous
#include <cuda_runtime.h>
#include <math.h>

#define NN        21
#define NN2       441
#define NFEAT     128
#define FC1_OUT   512
#define FC2_OUT   512
#define FC3_OUT   256
#define FC1_K     441
#define FC2_K     512
#define FC3_K     512

#define NBLOCKS   65          // block 0 = GCN, 1..64 = FC workers
#define NTHREADS  512

// ---- global scratch (allocation-free) ----
__device__ float g_v[448];            // GCN output (441 used)
__device__ float g_part1[4][512];     // FC1 partials [ksplit][out]
__device__ float g_part2[4][512];     // FC2 partials

// ---- grid barrier state (generation-based; self-resetting counter) ----
__device__ unsigned          g_cnt[4];
__device__ volatile unsigned g_flag[4];

__device__ __forceinline__ void gbar(int i) {
    __syncthreads();
    if (threadIdx.x == 0) {
        __threadfence();
        unsigned old = g_flag[i];
        if (atomicAdd(&g_cnt[i], 1u) == NBLOCKS - 1u) {
            g_cnt[i] = 0u;          // safe: all blocks have arrived
            __threadfence();
            atomicAdd((unsigned*)&g_flag[i], 1u);
        } else {
            while (g_flag[i] == old) { }
        }
        __threadfence();
    }
    __syncthreads();
}

// ---- dynamic smem layout (bytes) ----
// [0, 65536)        : FC3 weight slice (512x32 f32)  -- workers 0..7 only
//                     (aliased by the GCN scratch region for block 0)
// [65536, 79872)    : FC1 weight slice (111x32 max, padded)
// [79872, 96256)    : FC2 weight slice (128x32)
// [96256, 98304)    : x buffer (512 f32)
// [98304, 100352)   : reduction buffer (512 f32)
#define SMEM_BYTES 100352

__global__ void __launch_bounds__(NTHREADS, 1)
fused_net_kernel(const float* __restrict__ state,
                 const int*   __restrict__ edge_index, int n_edges,
                 const float* __restrict__ W1,  const float* __restrict__ b1,
                 const float* __restrict__ W2,  const float* __restrict__ b2,
                 const float* __restrict__ Wf1, const float* __restrict__ bf1,
                 const float* __restrict__ Wf2, const float* __restrict__ bf2,
                 const float* __restrict__ Wf3, const float* __restrict__ bf3,
                 float* __restrict__ out)
{
    extern __shared__ char smem[];
    float* w3s = (float*)(smem);                 // [512*32]
    float* w1s = (float*)(smem + 65536);         // [111*32 max]
    float* w2s = (float*)(smem + 79872);         // [128*32]
    float* sx  = (float*)(smem + 96256);         // [512]
    float* red = (float*)(smem + 98304);         // [512]

    const int t = threadIdx.x;

    if (blockIdx.x == 0) {
        // ================= GCN front-end (batch element 0 only) ===========
        float* sA    = (float*)(smem);            // 441
        float* sBufA = sA    + 448;               // 441
        float* sBufB = sBufA + 448;               // 441
        float* sX    = sBufB + 448;               // 21*128
        float* sW1g  = sX    + NN * NFEAT;        // 128*21
        float* sW2g  = sW1g  + NFEAT * NN;        // 441
        float* sb1   = sW2g  + 448;               // 21
        float* sb2   = sb1   + 32;                // 21
        float* sdinv = sb2   + 32;                // 21

        if (t < NN2) sA[t] = 0.f;
        __syncthreads();

        for (int e = t; e < n_edges; e += NTHREADS) {
            int r = edge_index[e];
            int c = edge_index[n_edges + e];
            atomicAdd(&sA[r * NN + c], 1.0f);
        }
        for (int i = t; i < NN * NFEAT; i += NTHREADS) sX[i]   = state[i];
        for (int i = t; i < NFEAT * NN; i += NTHREADS) sW1g[i] = W1[i];
        if (t < NN2) sW2g[t] = W2[t];
        if (t < NN) { sb1[t] = b1[t]; sb2[t] = b2[t]; }
        __syncthreads();

        if (t < NN) sA[t * NN + t] += 1.0f;
        __syncthreads();

        if (t < NN) {
            float d = 0.f;
            #pragma unroll
            for (int i = 0; i < NN; i++) d += sA[i * NN + t];
            sdinv[t] = (d > 0.f) ? rsqrtf(d) : 0.f;
        }
        __syncthreads();

        if (t < NN2) {
            int i = t / NN, j = t % NN;
            sA[t] *= sdinv[i] * sdinv[j];
        }
        __syncthreads();

        if (t < NN2) {                 // h1 = X @ W1
            int i = t / NN, j = t % NN;
            float acc = 0.f;
            #pragma unroll 8
            for (int f = 0; f < NFEAT; f++) acc += sX[i * NFEAT + f] * sW1g[f * NN + j];
            sBufA[t] = acc;
        }
        __syncthreads();

        if (t < NN2) {                 // g1 = A @ h1 + b1
            int i = t / NN, j = t % NN;
            float acc = sb1[j];
            #pragma unroll
            for (int k = 0; k < NN; k++) acc += sA[i * NN + k] * sBufA[k * NN + j];
            sBufB[t] = acc;
        }
        __syncthreads();

        if (t < NN2) {                 // h2 = g1 @ W2
            int i = t / NN, j = t % NN;
            float acc = 0.f;
            #pragma unroll
            for (int f = 0; f < NN; f++) acc += sBufB[i * NN + f] * sW2g[f * NN + j];
            sBufA[t] = acc;
        }
        __syncthreads();

        if (t < NN2) {                 // v = A @ h2 + b2
            int i = t / NN, j = t % NN;
            float acc = sb2[j];
            #pragma unroll
            for (int k = 0; k < NN; k++) acc += sA[i * NN + k] * sBufA[k * NN + j];
            g_v[t] = acc;
        }

        gbar(0);   // v ready
        gbar(1);   // (idle through FC stages)
        gbar(2);
        return;
    }

    // ======================= FC workers 1..64 =============================
    const int w   = blockIdx.x - 1;      // 0..63
    const int jt1 = w >> 2;              // FC1/FC2 jtile (0..15)
    const int ks  = w & 3;               // FC1/FC2 ksplit (0..3)

    // FC1 K-range: [ks*111, min(441, ks*111+111))
    const int k0_1  = ks * 111;
    const int len1  = min(FC1_K - k0_1, 111);
    // FC2 K-range: [ks*128, ks*128+128)
    const int k0_2  = ks * 128;

    // -------- preload weight slices into smem (overlaps GCN) --------
    for (int i = t; i < len1 * 32; i += NTHREADS)
        w1s[i] = Wf1[(k0_1 + (i >> 5)) * FC1_OUT + jt1 * 32 + (i & 31)];
    for (int i = t; i < 128 * 32; i += NTHREADS)
        w2s[i] = Wf2[(k0_2 + (i >> 5)) * FC2_OUT + jt1 * 32 + (i & 31)];
    if (w < 8) {   // FC3 workers: full-K slice, 32 outputs each
        for (int i = t; i < FC3_K * 32; i += NTHREADS)
            w3s[i] = Wf3[(i >> 5) * FC3_OUT + w * 32 + (i & 31)];
    }

    const int j  = t & 31;
    const int kg = t >> 5;               // 0..15

    gbar(0);   // wait for v

    // ---------------- FC1: partials over K-slice ----------------
    for (int i = t; i < len1; i += NTHREADS) sx[i] = __ldcg(&g_v[k0_1 + i]);
    __syncthreads();
    {
        float acc = 0.f;
        #pragma unroll 4
        for (int k = kg; k < len1; k += 16) acc += sx[k] * w1s[k * 32 + j];
        red[t] = acc;
    }
    __syncthreads();
    if (t < 32) {
        float s = red[t];
        #pragma unroll
        for (int g = 1; g < 16; g++) s += red[g * 32 + t];
        g_part1[ks][jt1 * 32 + t] = s;
    }

    gbar(1);

    // ---------------- FC2: x = relu(bf1 + sum partials) ----------------
    if (t < 128) {
        int k = k0_2 + t;
        float xv = __ldg(&bf1[k]);
        #pragma unroll
        for (int s = 0; s < 4; s++) xv += __ldcg(&g_part1[s][k]);
        sx[t] = fmaxf(xv, 0.f);
    }
    __syncthreads();
    {
        float acc = 0.f;
        #pragma unroll
        for (int k = kg; k < 128; k += 16) acc += sx[k] * w2s[k * 32 + j];
        red[t] = acc;
    }
    __syncthreads();
    if (t < 32) {
        float s = red[t];
        #pragma unroll
        for (int g = 1; g < 16; g++) s += red[g * 32 + t];
        g_part2[ks][jt1 * 32 + t] = s;
    }

    gbar(2);

    // ---------------- FC3: workers 0..7, full K, direct output ----------
    if (w < 8) {
        if (t < FC3_K) {
            float xv = __ldg(&bf2[t]);
            #pragma unroll
            for (int s = 0; s < 4; s++) xv += __ldcg(&g_part2[s][t]);
            sx[t] = fmaxf(xv, 0.f);
        }
        __syncthreads();
        float acc = 0.f;
        #pragma unroll 8
        for (int k = kg; k < FC3_K; k += 16) acc += sx[k] * w3s[k * 32 + j];
        red[t] = acc;
        __syncthreads();
        if (t < 32) {
            float s = red[t];
            #pragma unroll
            for (int g = 1; g < 16; g++) s += red[g * 32 + t];
            int oj = w * 32 + t;
            out[oj] = fmaxf(s + __ldg(&bf3[oj]), 0.f);
        }
    }
}

// ---------------------------------------------------------------------------
extern "C" void kernel_launch(void* const* d_in, const int* in_sizes, int n_in,
                              void* d_out, int out_size)
{
    const float* state = (const float*)d_in[0];
    const int*   edges = (const int*)  d_in[1];
    const int n_edges  = in_sizes[1] / 2;

    const float* W1  = (const float*)d_in[2];
    const float* b1  = (const float*)d_in[3];
    const float* W2  = (const float*)d_in[4];
    const float* b2  = (const float*)d_in[5];
    const float* Wf1 = (const float*)d_in[6];
    const float* bf1 = (const float*)d_in[7];
    const float* Wf2 = (const float*)d_in[8];
    const float* bf2 = (const float*)d_in[9];
    const float* Wf3 = (const float*)d_in[10];
    const float* bf3 = (const float*)d_in[11];
    float* out = (float*)d_out;

    static bool attr_set = false;
    if (!attr_set) {
        cudaFuncSetAttribute(fused_net_kernel,
                             cudaFuncAttributeMaxDynamicSharedMemorySize,
                             SMEM_BYTES);
        attr_set = true;
    }

    fused_net_kernel<<<NBLOCKS, NTHREADS, SMEM_BYTES>>>(
        state, edges, n_edges, W1, b1, W2, b2,
        Wf1, bf1, Wf2, bf2, Wf3, bf3, out);
}